// round 4
// baseline (speedup 1.0000x reference)
#include <cuda_runtime.h>
#include <cuda_bf16.h>
#include <math.h>

#define NN 100000
#define DD 64
#define EE 1000000
#define EPSM 1e-7f

// ---------------- scratch (static __device__, no allocation) ----------------
// Interleaved accumulator: per node, 16 groups q of {denom float4, numer float4}
// => node stride 128 floats; group base = (node*16+q)*8
__device__ float g_acc[(size_t)NN * 128];        // 51.2 MB
__device__ float g_h[(size_t)NN * 128];          // 51.2 MB hidden (pre-BN)
__device__ float g_bnsum[128], g_bnsumsq[128], g_bnscale[128], g_bnshift[128];

__device__ __forceinline__ void red_add_v4(float* p, float a, float b, float c, float d) {
    asm volatile("red.global.add.v4.f32 [%0], {%1,%2,%3,%4};"
                 :: "l"(p), "f"(a), "f"(b), "f"(c), "f"(d) : "memory");
}

// ---------------- launch 0: zero accumulator (51.2 MB) ----------------
__global__ void zero_acc_kernel() {
    unsigned i = blockIdx.x * blockDim.x + threadIdx.x;
    if (i < (unsigned)NN * 32u)   // 3.2M float4
        reinterpret_cast<float4*>(g_acc)[i] = make_float4(0.f, 0.f, 0.f, 0.f);
}

// ---------------- launch 1: zero bn sums ----------------
__global__ void zero_bn1_kernel() {
    int i = threadIdx.x;
    if (i < 128) g_bnsum[i] = 0.f;
}

// ---------------- launch 2: zero bn sumsq ----------------
__global__ void zero_bn2_kernel() {
    int i = threadIdx.x;
    if (i < 128) g_bnsumsq[i] = 0.f;
}

// ---------------- launch 3: edge pass (PROFILED SLOT) ----------------
// 16 threads per edge; softmax shift-invariance => no segment-max needed
// (msg = relu(x)+eps in [1e-7, ~6], exp cannot overflow).
__global__ void __launch_bounds__(256) edge_kernel(const float4* __restrict__ x4,
                                                   const int* __restrict__ src,
                                                   const int* __restrict__ dst) {
    unsigned idx = blockIdx.x * blockDim.x + threadIdx.x;
    if (idx >= (unsigned)EE * 16u) return;
    unsigned e = idx >> 4, q = idx & 15u;
    int s = __ldg(src + e);
    int t = __ldg(dst + e);
    float4 v = __ldg(x4 + (size_t)s * 16 + q);
    float m0 = fmaxf(v.x, 0.f) + EPSM;
    float m1 = fmaxf(v.y, 0.f) + EPSM;
    float m2 = fmaxf(v.z, 0.f) + EPSM;
    float m3 = fmaxf(v.w, 0.f) + EPSM;
    float e0 = __expf(m0), e1 = __expf(m1), e2 = __expf(m2), e3 = __expf(m3);
    float* base = g_acc + ((size_t)t * 16 + q) * 8;
    red_add_v4(base,     e0,      e1,      e2,      e3);        // denom
    red_add_v4(base + 4, m0 * e0, m1 * e1, m2 * e2, m3 * e3);   // numer
}

// ---------------- launch 4: agg finalize + residual + Linear1 + BN stats ----------------
// 64 nodes/block, 256 threads, thread tile = 8 nodes x 4 cols. FMA-bound.
__global__ void __launch_bounds__(256) nodeA_kernel(const float* __restrict__ x,
                                                    const float* __restrict__ W1,
                                                    const float* __restrict__ b1) {
    __shared__ float s_in[64 * 64];    // [n][k] 16 KB
    __shared__ float s_W1[64 * 128];   // [k][c] 32 KB
    int t = threadIdx.x;
    int nb = blockIdx.x * 64;

    for (int i = t; i < 64 * 128; i += 256) s_W1[i] = __ldg(W1 + i);
    for (int i = t; i < 64 * 64; i += 256) {
        int n = i >> 6, d = i & 63;
        int q = d >> 2, j = d & 3;
        float v = 0.f;
        if (nb + n < NN) {
            size_t gb = ((size_t)(nb + n) * 16 + q) * 8;
            float den = g_acc[gb + j];
            float num = g_acc[gb + 4 + j];
            v = num / (den + 1e-16f) + __ldg(x + (size_t)(nb + n) * 64 + d);
        }
        s_in[i] = v;
    }
    __syncthreads();

    int c0 = (t & 31) * 4;
    int n0 = (t >> 5) * 8;
    float acc[8][4];
    float b0 = __ldg(&b1[c0]), bb1 = __ldg(&b1[c0 + 1]), b2v = __ldg(&b1[c0 + 2]), b3 = __ldg(&b1[c0 + 3]);
#pragma unroll
    for (int i = 0; i < 8; i++) { acc[i][0] = b0; acc[i][1] = bb1; acc[i][2] = b2v; acc[i][3] = b3; }

#pragma unroll 4
    for (int k = 0; k < 64; k++) {
        float4 w = *reinterpret_cast<const float4*>(&s_W1[k * 128 + c0]);
#pragma unroll
        for (int i = 0; i < 8; i++) {
            float a = s_in[(n0 + i) * 64 + k];
            acc[i][0] = fmaf(a, w.x, acc[i][0]);
            acc[i][1] = fmaf(a, w.y, acc[i][1]);
            acc[i][2] = fmaf(a, w.z, acc[i][2]);
            acc[i][3] = fmaf(a, w.w, acc[i][3]);
        }
    }

    float su[4] = {0.f, 0.f, 0.f, 0.f}, sq[4] = {0.f, 0.f, 0.f, 0.f};
#pragma unroll
    for (int i = 0; i < 8; i++) {
        int n = nb + n0 + i;
        if (n < NN) {
            *reinterpret_cast<float4*>(&g_h[(size_t)n * 128 + c0]) =
                make_float4(acc[i][0], acc[i][1], acc[i][2], acc[i][3]);
#pragma unroll
            for (int j = 0; j < 4; j++) { su[j] += acc[i][j]; sq[j] = fmaf(acc[i][j], acc[i][j], sq[j]); }
        }
    }
#pragma unroll
    for (int j = 0; j < 4; j++) {
        atomicAdd(&g_bnsum[c0 + j], su[j]);
        atomicAdd(&g_bnsumsq[c0 + j], sq[j]);
    }
}

// ---------------- launch 5: BN finalize ----------------
__global__ void bnfin_kernel(const float* __restrict__ gam, const float* __restrict__ bet) {
    int c = threadIdx.x;
    float mean = g_bnsum[c] * (1.f / (float)NN);
    float var = g_bnsumsq[c] * (1.f / (float)NN) - mean * mean;
    float sc = __ldg(gam + c) * rsqrtf(var + 1e-5f);
    g_bnscale[c] = sc;
    g_bnshift[c] = __ldg(bet + c) - mean * sc;
}

// ---------------- launch 6: BN+ReLU + Linear2 + LayerNorm + ReLU ----------------
// 32 nodes/block, 256 threads, thread tile = 2 nodes x 4 cols.
__global__ void __launch_bounds__(256) nodeB_kernel(const float* __restrict__ W2,
                                                    const float* __restrict__ b2,
                                                    const float* __restrict__ lng,
                                                    const float* __restrict__ lnb,
                                                    float* __restrict__ out) {
    __shared__ float s_W2[128 * 64];   // [k][c] 32 KB
    __shared__ float s_a[32 * 128];    // [n][k] 16 KB (reused as s_y after matmul)
    int t = threadIdx.x;
    int nb = blockIdx.x * 32;

    for (int i = t; i < 128 * 64; i += 256) s_W2[i] = __ldg(W2 + i);
    for (int i = t; i < 32 * 128; i += 256) {
        int n = i >> 7, k = i & 127;
        float v = g_h[(size_t)(nb + n) * 128 + k];
        v = fmaf(v, g_bnscale[k], g_bnshift[k]);
        s_a[i] = fmaxf(v, 0.f);
    }
    __syncthreads();

    int c0 = (t & 15) * 4;
    int n0 = (t >> 4) * 2;
    float acc[2][4];
    float b0 = __ldg(&b2[c0]), bb1 = __ldg(&b2[c0 + 1]), b2v = __ldg(&b2[c0 + 2]), b3 = __ldg(&b2[c0 + 3]);
    acc[0][0] = b0; acc[0][1] = bb1; acc[0][2] = b2v; acc[0][3] = b3;
    acc[1][0] = b0; acc[1][1] = bb1; acc[1][2] = b2v; acc[1][3] = b3;

#pragma unroll 4
    for (int k = 0; k < 128; k++) {
        float4 w = *reinterpret_cast<const float4*>(&s_W2[k * 64 + c0]);
        float a0 = s_a[n0 * 128 + k];
        float a1 = s_a[(n0 + 1) * 128 + k];
        acc[0][0] = fmaf(a0, w.x, acc[0][0]);
        acc[0][1] = fmaf(a0, w.y, acc[0][1]);
        acc[0][2] = fmaf(a0, w.z, acc[0][2]);
        acc[0][3] = fmaf(a0, w.w, acc[0][3]);
        acc[1][0] = fmaf(a1, w.x, acc[1][0]);
        acc[1][1] = fmaf(a1, w.y, acc[1][1]);
        acc[1][2] = fmaf(a1, w.z, acc[1][2]);
        acc[1][3] = fmaf(a1, w.w, acc[1][3]);
    }
    __syncthreads();

    float* s_y = s_a;  // reuse as [n][64]
#pragma unroll
    for (int i = 0; i < 2; i++)
        *reinterpret_cast<float4*>(&s_y[(n0 + i) * 64 + c0]) =
            make_float4(acc[i][0], acc[i][1], acc[i][2], acc[i][3]);
    __syncthreads();

    int w = t >> 5, lane = t & 31;
#pragma unroll
    for (int nn = 0; nn < 4; nn++) {
        int n = w * 4 + nn;
        float v0 = s_y[n * 64 + lane];
        float v1 = s_y[n * 64 + lane + 32];
        float sum = v0 + v1;
        float sq = v0 * v0 + v1 * v1;
#pragma unroll
        for (int o = 16; o > 0; o >>= 1) {
            sum += __shfl_xor_sync(0xFFFFFFFFu, sum, o);
            sq  += __shfl_xor_sync(0xFFFFFFFFu, sq, o);
        }
        float mean = sum * (1.f / 64.f);
        float var = sq * (1.f / 64.f) - mean * mean;
        float inv = rsqrtf(var + 1e-5f);
        size_t g = (size_t)(nb + n) * 64;
        float y0 = (v0 - mean) * inv * __ldg(lng + lane) + __ldg(lnb + lane);
        float y1 = (v1 - mean) * inv * __ldg(lng + lane + 32) + __ldg(lnb + lane + 32);
        out[g + lane] = fmaxf(y0, 0.f);
        out[g + lane + 32] = fmaxf(y1, 0.f);
    }
}

// ---------------- launcher ----------------
extern "C" void kernel_launch(void* const* d_in, const int* in_sizes, int n_in,
                              void* d_out, int out_size) {
    const float* x   = (const float*)d_in[0];
    const int*   ei  = (const int*)d_in[1];
    const float* W1  = (const float*)d_in[2];
    const float* b1  = (const float*)d_in[3];
    const float* bng = (const float*)d_in[4];
    const float* bnb = (const float*)d_in[5];
    const float* W2  = (const float*)d_in[6];
    const float* b2  = (const float*)d_in[7];
    const float* lng = (const float*)d_in[8];
    const float* lnb = (const float*)d_in[9];
    float* out = (float*)d_out;

    const int* src = ei;        // edge_index[0]
    const int* dst = ei + EE;   // edge_index[1]

    // launch order chosen so edge_kernel is the 4th launch (profiled slot)
    zero_acc_kernel<<<((unsigned)NN * 32u + 255) / 256, 256>>>();          // 0
    zero_bn1_kernel<<<1, 128>>>();                                         // 1
    zero_bn2_kernel<<<1, 128>>>();                                         // 2
    edge_kernel<<<((unsigned)EE * 16u + 255) / 256, 256>>>(                // 3
        (const float4*)x, src, dst);
    nodeA_kernel<<<(NN + 63) / 64, 256>>>(x, W1, b1);                      // 4
    bnfin_kernel<<<1, 128>>>(bng, bnb);                                    // 5
    nodeB_kernel<<<(NN + 31) / 32, 256>>>(W2, b2, lng, lnb, out);          // 6
}

// round 6
// speedup vs baseline: 1.9930x; 1.9930x over previous
#include <cuda_runtime.h>
#include <cuda_bf16.h>
#include <math.h>

#define NN 100000
#define DD 64
#define EE 1000000
#define EPSM 1e-7f
#define NBLKA 1563   // ceil(NN/64)

// ---------------- scratch (static __device__, no allocation) ----------------
// Interleaved accumulator: per node, 16 groups q of {denom float4, numer float4}
__device__ float g_acc[(size_t)NN * 128];        // 51.2 MB
__device__ float g_h[(size_t)NN * 128];          // 51.2 MB hidden (pre-BN)
__device__ float g_part[(size_t)NBLKA * 256];    // 1.6 MB per-block BN partials
__device__ float g_bnscale[128], g_bnshift[128];
__device__ float g_dummy[32];

__device__ __forceinline__ void red_add_v4(float* p, float a, float b, float c, float d) {
    asm volatile("red.global.add.v4.f32 [%0], {%1,%2,%3,%4};"
                 :: "l"(p), "f"(a), "f"(b), "f"(c), "f"(d) : "memory");
}

// ---------------- launch 0: zero accumulator (51.2 MB) ----------------
__global__ void zero_acc_kernel() {
    unsigned i = blockIdx.x * blockDim.x + threadIdx.x;
    if (i < (unsigned)NN * 32u)
        reinterpret_cast<float4*>(g_acc)[i] = make_float4(0.f, 0.f, 0.f, 0.f);
}

// ---------------- launch 1: dummy (keeps nodeA at profiled launch index 3) ----------------
__global__ void dummy_kernel() {
    if (threadIdx.x < 32) g_dummy[threadIdx.x] = 0.f;
}

// ---------------- launch 2: edge pass (measured 141us, unchanged) ----------------
__global__ void __launch_bounds__(256) edge_kernel(const float4* __restrict__ x4,
                                                   const int* __restrict__ src,
                                                   const int* __restrict__ dst) {
    unsigned idx = blockIdx.x * blockDim.x + threadIdx.x;
    if (idx >= (unsigned)EE * 16u) return;
    unsigned e = idx >> 4, q = idx & 15u;
    int s = __ldg(src + e);
    int t = __ldg(dst + e);
    float4 v = __ldg(x4 + (size_t)s * 16 + q);
    float m0 = fmaxf(v.x, 0.f) + EPSM;
    float m1 = fmaxf(v.y, 0.f) + EPSM;
    float m2 = fmaxf(v.z, 0.f) + EPSM;
    float m3 = fmaxf(v.w, 0.f) + EPSM;
    float e0 = __expf(m0), e1 = __expf(m1), e2 = __expf(m2), e3 = __expf(m3);
    float* base = g_acc + ((size_t)t * 16 + q) * 8;
    red_add_v4(base,     e0,      e1,      e2,      e3);        // denom
    red_add_v4(base + 4, m0 * e0, m1 * e1, m2 * e2, m3 * e3);   // numer
}

// ---------------- launch 3 (PROFILED): agg + residual + Linear1 + BN partials ----------------
// 64 nodes/block, 256 threads, thread tile = 8 nodes x 4 cols. NO global atomics.
__global__ void __launch_bounds__(256) nodeA_kernel(const float* __restrict__ x,
                                                    const float* __restrict__ W1,
                                                    const float* __restrict__ b1) {
    __shared__ __align__(16) float s_in[64 * 64];    // [n][k] 16 KB (reused for reduction)
    __shared__ __align__(16) float s_W1[64 * 128];   // [k][c] 32 KB
    int t = threadIdx.x;
    int nb = blockIdx.x * 64;

    for (int i = t; i < 64 * 128; i += 256) s_W1[i] = __ldg(W1 + i);
    for (int i = t; i < 64 * 64; i += 256) {
        int n = i >> 6, d = i & 63;
        int q = d >> 2, j = d & 3;
        float v = 0.f;
        if (nb + n < NN) {
            size_t gb = ((size_t)(nb + n) * 16 + q) * 8;
            float den = g_acc[gb + j];
            float num = g_acc[gb + 4 + j];
            v = num / (den + 1e-16f) + __ldg(x + (size_t)(nb + n) * 64 + d);
        }
        s_in[i] = v;
    }
    __syncthreads();

    int c0 = (t & 31) * 4;
    int n0 = (t >> 5) * 8;
    int w  = t >> 5;
    float acc[8][4];
    float b0 = __ldg(&b1[c0]), bb1 = __ldg(&b1[c0 + 1]), b2v = __ldg(&b1[c0 + 2]), b3 = __ldg(&b1[c0 + 3]);
#pragma unroll
    for (int i = 0; i < 8; i++) { acc[i][0] = b0; acc[i][1] = bb1; acc[i][2] = b2v; acc[i][3] = b3; }

#pragma unroll 4
    for (int k = 0; k < 64; k++) {
        float4 wv = *reinterpret_cast<const float4*>(&s_W1[k * 128 + c0]);
#pragma unroll
        for (int i = 0; i < 8; i++) {
            float a = s_in[(n0 + i) * 64 + k];
            acc[i][0] = fmaf(a, wv.x, acc[i][0]);
            acc[i][1] = fmaf(a, wv.y, acc[i][1]);
            acc[i][2] = fmaf(a, wv.z, acc[i][2]);
            acc[i][3] = fmaf(a, wv.w, acc[i][3]);
        }
    }

    float su[4] = {0.f, 0.f, 0.f, 0.f}, sq[4] = {0.f, 0.f, 0.f, 0.f};
#pragma unroll
    for (int i = 0; i < 8; i++) {
        int n = nb + n0 + i;
        if (n < NN) {
            *reinterpret_cast<float4*>(&g_h[(size_t)n * 128 + c0]) =
                make_float4(acc[i][0], acc[i][1], acc[i][2], acc[i][3]);
#pragma unroll
            for (int j = 0; j < 4; j++) { su[j] += acc[i][j]; sq[j] = fmaf(acc[i][j], acc[i][j], sq[j]); }
        }
    }

    // block-level BN partial reduction via smem (reuse s_in); one coalesced
    // write per block -- zero global atomics.
    __syncthreads();
    float* s_sum = s_in;            // [8][128]
    float* s_sq  = s_in + 1024;     // [8][128]
#pragma unroll
    for (int j = 0; j < 4; j++) {
        s_sum[w * 128 + c0 + j] = su[j];
        s_sq [w * 128 + c0 + j] = sq[j];
    }
    __syncthreads();
    if (t < 128) {
        float a = 0.f, b = 0.f;
#pragma unroll
        for (int ww = 0; ww < 8; ww++) { a += s_sum[ww * 128 + t]; b += s_sq[ww * 128 + t]; }
        g_part[(size_t)blockIdx.x * 256 + t]       = a;
        g_part[(size_t)blockIdx.x * 256 + 128 + t] = b;
    }
}

// ---------------- launch 4: BN finalize (reduce partials) ----------------
__global__ void __launch_bounds__(128) bnfin_kernel(const float* __restrict__ gam,
                                                    const float* __restrict__ bet) {
    int c = threadIdx.x;
    float s = 0.f, q = 0.f;
    for (int b = 0; b < NBLKA; b++) {
        s += g_part[(size_t)b * 256 + c];
        q += g_part[(size_t)b * 256 + 128 + c];
    }
    float mean = s * (1.f / (float)NN);
    float var = q * (1.f / (float)NN) - mean * mean;
    float sc = __ldg(gam + c) * rsqrtf(var + 1e-5f);
    g_bnscale[c] = sc;
    g_bnshift[c] = __ldg(bet + c) - mean * sc;
}

// ---------------- launch 5: BN+ReLU + Linear2 + LayerNorm + ReLU ----------------
// 64 nodes/block, 256 threads, thread tile = 4 nodes x 4 cols.
// DYNAMIC smem: [0,32KB) W2 [k][c], [32KB,64KB) activations [n][k] (reused as s_y).
__global__ void __launch_bounds__(256) nodeB_kernel(const float* __restrict__ W2,
                                                    const float* __restrict__ b2,
                                                    const float* __restrict__ lng,
                                                    const float* __restrict__ lnb,
                                                    float* __restrict__ out) {
    extern __shared__ __align__(16) float smem[];
    float* s_W2 = smem;            // 128*64 = 8192 floats
    float* s_a  = smem + 8192;     // 64*128 = 8192 floats
    int t = threadIdx.x;
    int nb = blockIdx.x * 64;

    for (int i = t; i < 128 * 64; i += 256) s_W2[i] = __ldg(W2 + i);
    for (int i = t; i < 64 * 128; i += 256) {
        int n = i >> 7, k = i & 127;
        float v = 0.f;
        if (nb + n < NN) {
            v = g_h[(size_t)(nb + n) * 128 + k];
            v = fmaf(v, g_bnscale[k], g_bnshift[k]);
            v = fmaxf(v, 0.f);
        }
        s_a[i] = v;
    }
    __syncthreads();

    int c0 = (t & 15) * 4;
    int n0 = (t >> 4) * 4;
    float acc[4][4];
    float b0 = __ldg(&b2[c0]), bb1 = __ldg(&b2[c0 + 1]), b2v = __ldg(&b2[c0 + 2]), b3 = __ldg(&b2[c0 + 3]);
#pragma unroll
    for (int i = 0; i < 4; i++) { acc[i][0] = b0; acc[i][1] = bb1; acc[i][2] = b2v; acc[i][3] = b3; }

#pragma unroll 4
    for (int k = 0; k < 128; k++) {
        float4 wv = *reinterpret_cast<const float4*>(&s_W2[k * 64 + c0]);
#pragma unroll
        for (int i = 0; i < 4; i++) {
            float a = s_a[(n0 + i) * 128 + k];
            acc[i][0] = fmaf(a, wv.x, acc[i][0]);
            acc[i][1] = fmaf(a, wv.y, acc[i][1]);
            acc[i][2] = fmaf(a, wv.z, acc[i][2]);
            acc[i][3] = fmaf(a, wv.w, acc[i][3]);
        }
    }
    __syncthreads();   // everyone done reading s_a

    float* s_y = s_a;  // reuse as [n][64]
#pragma unroll
    for (int i = 0; i < 4; i++)
        *reinterpret_cast<float4*>(&s_y[(n0 + i) * 64 + c0]) =
            make_float4(acc[i][0], acc[i][1], acc[i][2], acc[i][3]);
    __syncthreads();

    // LayerNorm + ReLU: warp w handles nodes 8w..8w+7
    int w = t >> 5, lane = t & 31;
#pragma unroll
    for (int nn = 0; nn < 8; nn++) {
        int n = w * 8 + nn;
        if (nb + n >= NN) break;
        float v0 = s_y[n * 64 + lane];
        float v1 = s_y[n * 64 + lane + 32];
        float sum = v0 + v1;
        float sq = v0 * v0 + v1 * v1;
#pragma unroll
        for (int o = 16; o > 0; o >>= 1) {
            sum += __shfl_xor_sync(0xFFFFFFFFu, sum, o);
            sq  += __shfl_xor_sync(0xFFFFFFFFu, sq, o);
        }
        float mean = sum * (1.f / 64.f);
        float var = sq * (1.f / 64.f) - mean * mean;
        float inv = rsqrtf(var + 1e-5f);
        size_t g = (size_t)(nb + n) * 64;
        float y0 = (v0 - mean) * inv * __ldg(lng + lane) + __ldg(lnb + lane);
        float y1 = (v1 - mean) * inv * __ldg(lng + lane + 32) + __ldg(lnb + lane + 32);
        out[g + lane] = fmaxf(y0, 0.f);
        out[g + lane + 32] = fmaxf(y1, 0.f);
    }
}

// ---------------- launcher ----------------
extern "C" void kernel_launch(void* const* d_in, const int* in_sizes, int n_in,
                              void* d_out, int out_size) {
    const float* x   = (const float*)d_in[0];
    const int*   ei  = (const int*)d_in[1];
    const float* W1  = (const float*)d_in[2];
    const float* b1  = (const float*)d_in[3];
    const float* bng = (const float*)d_in[4];
    const float* bnb = (const float*)d_in[5];
    const float* W2  = (const float*)d_in[6];
    const float* b2  = (const float*)d_in[7];
    const float* lng = (const float*)d_in[8];
    const float* lnb = (const float*)d_in[9];
    float* out = (float*)d_out;

    const int* src = ei;        // edge_index[0]
    const int* dst = ei + EE;   // edge_index[1]

    const int NODEB_SMEM = 64 * 1024;
    cudaFuncSetAttribute(nodeB_kernel,
                         cudaFuncAttributeMaxDynamicSharedMemorySize, NODEB_SMEM);

    zero_acc_kernel<<<((unsigned)NN * 32u + 255) / 256, 256>>>();          // 0
    dummy_kernel<<<1, 32>>>();                                             // 1
    edge_kernel<<<((unsigned)EE * 16u + 255) / 256, 256>>>(                // 2
        (const float4*)x, src, dst);
    nodeA_kernel<<<NBLKA, 256>>>(x, W1, b1);                               // 3 (profiled)
    bnfin_kernel<<<1, 128>>>(bng, bnb);                                    // 4
    nodeB_kernel<<<(NN + 63) / 64, 256, NODEB_SMEM>>>(W2, b2, lng, lnb, out); // 5
}

// round 7
// speedup vs baseline: 2.4545x; 1.2315x over previous
#include <cuda_runtime.h>
#include <cuda_bf16.h>
#include <math.h>

#define NN 100000
#define DD 64
#define EE 1000000
#define EPSM 1e-7f
#define NBLKA 1563   // ceil(NN/64)

// ---------------- scratch (static __device__, no allocation) ----------------
__device__ int   g_count[NN];
__device__ int   g_incl[NN];
__device__ int   g_bsum[128];
__device__ int   g_offset[NN + 1];
__device__ int   g_cursor[NN];
__device__ int   g_ssrc[EE];
__device__ float g_aggout[(size_t)NN * DD];      // 25.6 MB (agg + residual)
__device__ float g_h[(size_t)NN * 128];          // 51.2 MB hidden (pre-BN)
__device__ float g_part[(size_t)NBLKA * 256];    // per-block BN partials
__device__ float g_bnscale[128], g_bnshift[128];

// ---------------- packed f32x2 helpers ----------------
__device__ __forceinline__ unsigned long long pack2(float x, float y) {
    unsigned long long d;
    asm("mov.b64 %0, {%1, %2};" : "=l"(d) : "f"(x), "f"(y));
    return d;
}
__device__ __forceinline__ void unpack2(unsigned long long v, float& a, float& b) {
    asm("mov.b64 {%0, %1}, %2;" : "=f"(a), "=f"(b) : "l"(v));
}
__device__ __forceinline__ unsigned long long fma2(unsigned long long a,
                                                   unsigned long long b,
                                                   unsigned long long c) {
    unsigned long long d;
    asm("fma.rn.f32x2 %0, %1, %2, %3;" : "=l"(d) : "l"(a), "l"(b), "l"(c));
    return d;
}

// ---------------- 0: zero counters ----------------
__global__ void zero_kernel() {
    unsigned i = blockIdx.x * blockDim.x + threadIdx.x;
    if (i < NN) g_count[i] = 0;
}

// ---------------- 1: histogram of dst ----------------
__global__ void hist_kernel(const int* __restrict__ dst) {
    unsigned e = blockIdx.x * blockDim.x + threadIdx.x;
    if (e < EE) atomicAdd(&g_count[__ldg(dst + e)], 1);
}

// ---------------- 2: per-1024-block inclusive scan ----------------
__global__ void scan1_kernel() {
    __shared__ int s[1024];
    int t = threadIdx.x;
    int i = blockIdx.x * 1024 + t;
    int c = (i < NN) ? g_count[i] : 0;
    s[t] = c;
    __syncthreads();
#pragma unroll
    for (int d = 1; d < 1024; d <<= 1) {
        int v = (t >= d) ? s[t - d] : 0;
        __syncthreads();
        s[t] += v;
        __syncthreads();
    }
    if (i < NN) g_incl[i] = s[t];
    if (t == 1023) g_bsum[blockIdx.x] = s[1023];
}

// ---------------- 3: finalize offsets + cursors (block-prefix fused in) ----------------
__global__ void scan3_kernel() {
    __shared__ int sh[256];
    int t = threadIdx.x;
    int g = blockIdx.x >> 2;           // which 1024-group this 256-block belongs to
    sh[t] = (t < g) ? g_bsum[t] : 0;   // g <= 97 < 256
    __syncthreads();
#pragma unroll
    for (int d = 128; d > 0; d >>= 1) {
        if (t < d) sh[t] += sh[t + d];
        __syncthreads();
    }
    int pref = sh[0];
    unsigned i = blockIdx.x * 256 + t;
    if (i < NN) {
        int incl = g_incl[i] + pref;
        g_offset[i + 1] = incl;
        g_cursor[i] = incl - g_count[i];
        if (i == 0) g_offset[0] = 0;
    }
}

// ---------------- 4: scatter edges into CSR order ----------------
__global__ void scatter_kernel(const int* __restrict__ src, const int* __restrict__ dst) {
    unsigned e = blockIdx.x * blockDim.x + threadIdx.x;
    if (e >= EE) return;
    int d = __ldg(dst + e);
    int pos = atomicAdd(&g_cursor[d], 1);
    g_ssrc[pos] = __ldg(src + e);
}

// ---------------- 5: gather-aggregate (warp per node) + residual ----------------
__global__ void __launch_bounds__(256) agg_kernel(const float2* __restrict__ x2) {
    int gw = (blockIdx.x * 256 + threadIdx.x) >> 5;   // node id (uniform per warp)
    int lane = threadIdx.x & 31;
    if (gw >= NN) return;
    int beg = g_offset[gw], end = g_offset[gw + 1];
    float d0 = 0.f, d1 = 0.f, s0 = 0.f, s1 = 0.f;
    for (int base = beg; base < end; base += 32) {
        int m = end - base; if (m > 32) m = 32;
        int sl = (lane < m) ? __ldg(g_ssrc + base + lane) : 0;
#pragma unroll 4
        for (int i = 0; i < m; i++) {
            int s = __shfl_sync(0xFFFFFFFFu, sl, i);
            float2 v = __ldg(x2 + (size_t)s * 32 + lane);
            float m0 = fmaxf(v.x, 0.f) + EPSM;
            float m1 = fmaxf(v.y, 0.f) + EPSM;
            float e0 = __expf(m0), e1 = __expf(m1);
            d0 += e0; d1 += e1;
            s0 = fmaf(m0, e0, s0); s1 = fmaf(m1, e1, s1);
        }
    }
    float2 self = __ldg(x2 + (size_t)gw * 32 + lane);
    float2 r;
    r.x = s0 / (d0 + 1e-16f) + self.x;
    r.y = s1 / (d1 + 1e-16f) + self.y;
    reinterpret_cast<float2*>(g_aggout)[(size_t)gw * 32 + lane] = r;
}

// ---------------- 6: Linear1 (f32x2) + BN partials ----------------
// 64 nodes/block, 256 threads. Warp w -> nodes w*8..w*8+7 (4 node-pairs),
// lane -> 4 cols. Activations transposed [k][n] pad 66. Dynamic smem 49664 B.
__global__ void __launch_bounds__(256) nodeA_kernel(const float* __restrict__ W1,
                                                    const float* __restrict__ b1) {
    extern __shared__ __align__(16) float sm[];
    float* s_W1  = sm;            // 8192 floats [k][c]
    float* s_inT = sm + 8192;     // 64*66 = 4224 floats [k][n]
    int t = threadIdx.x;
    int nb = blockIdx.x * 64;

    for (int i = t; i < 8192; i += 256) s_W1[i] = __ldg(W1 + i);
    for (int i = t; i < 4096; i += 256) {
        int n = i >> 6, k = i & 63;
        float v = (nb + n < NN) ? g_aggout[(size_t)(nb + n) * 64 + k] : 0.f;
        s_inT[k * 66 + n] = v;
    }
    __syncthreads();

    int lane = t & 31, w = t >> 5;
    int c0 = lane * 4;
    int n0 = w * 8;
    unsigned long long acc[4][4];
    {
        float b0 = __ldg(b1 + c0), bv1 = __ldg(b1 + c0 + 1);
        float bv2 = __ldg(b1 + c0 + 2), bv3 = __ldg(b1 + c0 + 3);
        unsigned long long i0 = pack2(b0, b0), i1 = pack2(bv1, bv1);
        unsigned long long i2 = pack2(bv2, bv2), i3 = pack2(bv3, bv3);
#pragma unroll
        for (int p = 0; p < 4; p++) { acc[p][0] = i0; acc[p][1] = i1; acc[p][2] = i2; acc[p][3] = i3; }
    }

#pragma unroll 4
    for (int k = 0; k < 64; k++) {
        float4 wv = *reinterpret_cast<const float4*>(&s_W1[k * 128 + c0]);
        unsigned long long w0 = pack2(wv.x, wv.x), w1 = pack2(wv.y, wv.y);
        unsigned long long w2 = pack2(wv.z, wv.z), w3 = pack2(wv.w, wv.w);
        const float* rp = &s_inT[k * 66 + n0];
        unsigned long long a0 = *reinterpret_cast<const unsigned long long*>(rp);
        unsigned long long a1 = *reinterpret_cast<const unsigned long long*>(rp + 2);
        unsigned long long a2 = *reinterpret_cast<const unsigned long long*>(rp + 4);
        unsigned long long a3 = *reinterpret_cast<const unsigned long long*>(rp + 6);
        acc[0][0] = fma2(a0, w0, acc[0][0]); acc[0][1] = fma2(a0, w1, acc[0][1]);
        acc[0][2] = fma2(a0, w2, acc[0][2]); acc[0][3] = fma2(a0, w3, acc[0][3]);
        acc[1][0] = fma2(a1, w0, acc[1][0]); acc[1][1] = fma2(a1, w1, acc[1][1]);
        acc[1][2] = fma2(a1, w2, acc[1][2]); acc[1][3] = fma2(a1, w3, acc[1][3]);
        acc[2][0] = fma2(a2, w0, acc[2][0]); acc[2][1] = fma2(a2, w1, acc[2][1]);
        acc[2][2] = fma2(a2, w2, acc[2][2]); acc[2][3] = fma2(a2, w3, acc[2][3]);
        acc[3][0] = fma2(a3, w0, acc[3][0]); acc[3][1] = fma2(a3, w1, acc[3][1]);
        acc[3][2] = fma2(a3, w2, acc[3][2]); acc[3][3] = fma2(a3, w3, acc[3][3]);
    }

    float su[4] = {0.f, 0.f, 0.f, 0.f}, sq[4] = {0.f, 0.f, 0.f, 0.f};
#pragma unroll
    for (int p = 0; p < 4; p++) {
        float e0, o0, e1, o1, e2, o2, e3, o3;
        unpack2(acc[p][0], e0, o0); unpack2(acc[p][1], e1, o1);
        unpack2(acc[p][2], e2, o2); unpack2(acc[p][3], e3, o3);
        int ne = nb + n0 + 2 * p;
        if (ne < NN) {
            *reinterpret_cast<float4*>(&g_h[(size_t)ne * 128 + c0]) = make_float4(e0, e1, e2, e3);
            su[0] += e0; sq[0] = fmaf(e0, e0, sq[0]);
            su[1] += e1; sq[1] = fmaf(e1, e1, sq[1]);
            su[2] += e2; sq[2] = fmaf(e2, e2, sq[2]);
            su[3] += e3; sq[3] = fmaf(e3, e3, sq[3]);
        }
        int no = ne + 1;
        if (no < NN) {
            *reinterpret_cast<float4*>(&g_h[(size_t)no * 128 + c0]) = make_float4(o0, o1, o2, o3);
            su[0] += o0; sq[0] = fmaf(o0, o0, sq[0]);
            su[1] += o1; sq[1] = fmaf(o1, o1, sq[1]);
            su[2] += o2; sq[2] = fmaf(o2, o2, sq[2]);
            su[3] += o3; sq[3] = fmaf(o3, o3, sq[3]);
        }
    }

    // block-level BN partial reduction via smem (reuse sm[0..2048)); one
    // coalesced write per block, zero global atomics.
    __syncthreads();
    float* s_sum = sm;           // [8][128]
    float* s_sq  = sm + 1024;    // [8][128]
#pragma unroll
    for (int j = 0; j < 4; j++) {
        s_sum[w * 128 + c0 + j] = su[j];
        s_sq [w * 128 + c0 + j] = sq[j];
    }
    __syncthreads();
    if (t < 128) {
        float a = 0.f, b = 0.f;
#pragma unroll
        for (int ww = 0; ww < 8; ww++) { a += s_sum[ww * 128 + t]; b += s_sq[ww * 128 + t]; }
        g_part[(size_t)blockIdx.x * 256 + t]       = a;
        g_part[(size_t)blockIdx.x * 256 + 128 + t] = b;
    }
}

// ---------------- 7: BN finalize (reduce partials) ----------------
__global__ void __launch_bounds__(128) bnfin_kernel(const float* __restrict__ gam,
                                                    const float* __restrict__ bet) {
    int c = threadIdx.x;
    float s = 0.f, q = 0.f;
#pragma unroll 4
    for (int b = 0; b < NBLKA; b++) {
        s += g_part[(size_t)b * 256 + c];
        q += g_part[(size_t)b * 256 + 128 + c];
    }
    float mean = s * (1.f / (float)NN);
    float var = q * (1.f / (float)NN) - mean * mean;
    float sc = __ldg(gam + c) * rsqrtf(var + 1e-5f);
    g_bnscale[c] = sc;
    g_bnshift[c] = __ldg(bet + c) - mean * sc;
}

// ---------------- 8: BN+ReLU + Linear2 (f32x2) + LayerNorm + ReLU ----------------
// 64 nodes/block, 256 threads. Warp w -> nodes w*8..w*8+7, lane -> 2 cols.
// Dynamic smem: s_W2 8192 + s_aT 128*66=8448 floats = 66560 B.
__global__ void __launch_bounds__(256) nodeB_kernel(const float* __restrict__ W2,
                                                    const float* __restrict__ b2,
                                                    const float* __restrict__ lng,
                                                    const float* __restrict__ lnb,
                                                    float* __restrict__ out) {
    extern __shared__ __align__(16) float sm[];
    float* s_W2 = sm;            // 8192 floats [k][c]
    float* s_aT = sm + 8192;     // 128*66 floats [k][n] (reused as s_y)
    int t = threadIdx.x;
    int nb = blockIdx.x * 64;

    for (int i = t; i < 8192; i += 256) s_W2[i] = __ldg(W2 + i);
    for (int i = t; i < 8192; i += 256) {
        int n = i >> 7, k = i & 127;
        float v = 0.f;
        if (nb + n < NN) {
            v = g_h[(size_t)(nb + n) * 128 + k];
            v = fmaf(v, g_bnscale[k], g_bnshift[k]);
            v = fmaxf(v, 0.f);
        }
        s_aT[k * 66 + n] = v;
    }
    __syncthreads();

    int lane = t & 31, w = t >> 5;
    int c0 = lane * 2;
    int n0 = w * 8;
    unsigned long long acc[4][2];
    {
        float b0 = __ldg(b2 + c0), bv1 = __ldg(b2 + c0 + 1);
        unsigned long long i0 = pack2(b0, b0), i1 = pack2(bv1, bv1);
#pragma unroll
        for (int p = 0; p < 4; p++) { acc[p][0] = i0; acc[p][1] = i1; }
    }

#pragma unroll 4
    for (int k = 0; k < 128; k++) {
        float2 wv = *reinterpret_cast<const float2*>(&s_W2[k * 64 + c0]);
        unsigned long long w0 = pack2(wv.x, wv.x), w1 = pack2(wv.y, wv.y);
        const float* rp = &s_aT[k * 66 + n0];
        unsigned long long a0 = *reinterpret_cast<const unsigned long long*>(rp);
        unsigned long long a1 = *reinterpret_cast<const unsigned long long*>(rp + 2);
        unsigned long long a2 = *reinterpret_cast<const unsigned long long*>(rp + 4);
        unsigned long long a3 = *reinterpret_cast<const unsigned long long*>(rp + 6);
        acc[0][0] = fma2(a0, w0, acc[0][0]); acc[0][1] = fma2(a0, w1, acc[0][1]);
        acc[1][0] = fma2(a1, w0, acc[1][0]); acc[1][1] = fma2(a1, w1, acc[1][1]);
        acc[2][0] = fma2(a2, w0, acc[2][0]); acc[2][1] = fma2(a2, w1, acc[2][1]);
        acc[3][0] = fma2(a3, w0, acc[3][0]); acc[3][1] = fma2(a3, w1, acc[3][1]);
    }
    __syncthreads();   // all warps done reading s_aT / s_W2

    float* s_y = sm + 8192;  // reuse as [64][64]
#pragma unroll
    for (int p = 0; p < 4; p++) {
        float e0, o0, e1, o1;
        unpack2(acc[p][0], e0, o0);
        unpack2(acc[p][1], e1, o1);
        int nloc = n0 + 2 * p;
        s_y[nloc * 64 + c0]     = e0;
        s_y[nloc * 64 + c0 + 1] = e1;
        s_y[(nloc + 1) * 64 + c0]     = o0;
        s_y[(nloc + 1) * 64 + c0 + 1] = o1;
    }
    __syncthreads();

    // LayerNorm + ReLU: warp w handles nodes w*8..w*8+7
#pragma unroll
    for (int nn = 0; nn < 8; nn++) {
        int n = w * 8 + nn;
        if (nb + n >= NN) break;
        float v0 = s_y[n * 64 + lane];
        float v1 = s_y[n * 64 + lane + 32];
        float sum = v0 + v1;
        float sq = v0 * v0 + v1 * v1;
#pragma unroll
        for (int o = 16; o > 0; o >>= 1) {
            sum += __shfl_xor_sync(0xFFFFFFFFu, sum, o);
            sq  += __shfl_xor_sync(0xFFFFFFFFu, sq, o);
        }
        float mean = sum * (1.f / 64.f);
        float var = sq * (1.f / 64.f) - mean * mean;
        float inv = rsqrtf(var + 1e-5f);
        size_t g = (size_t)(nb + n) * 64;
        float y0 = (v0 - mean) * inv * __ldg(lng + lane) + __ldg(lnb + lane);
        float y1 = (v1 - mean) * inv * __ldg(lng + lane + 32) + __ldg(lnb + lane + 32);
        out[g + lane] = fmaxf(y0, 0.f);
        out[g + lane + 32] = fmaxf(y1, 0.f);
    }
}

// ---------------- launcher ----------------
extern "C" void kernel_launch(void* const* d_in, const int* in_sizes, int n_in,
                              void* d_out, int out_size) {
    const float* x   = (const float*)d_in[0];
    const int*   ei  = (const int*)d_in[1];
    const float* W1  = (const float*)d_in[2];
    const float* b1  = (const float*)d_in[3];
    const float* bng = (const float*)d_in[4];
    const float* bnb = (const float*)d_in[5];
    const float* W2  = (const float*)d_in[6];
    const float* b2  = (const float*)d_in[7];
    const float* lng = (const float*)d_in[8];
    const float* lnb = (const float*)d_in[9];
    float* out = (float*)d_out;

    const int* src = ei;        // edge_index[0]
    const int* dst = ei + EE;   // edge_index[1]

    const int NODEA_SMEM = (8192 + 64 * 66) * 4;    // 49664 B
    const int NODEB_SMEM = (8192 + 128 * 66) * 4;   // 66560 B
    cudaFuncSetAttribute(nodeA_kernel, cudaFuncAttributeMaxDynamicSharedMemorySize, NODEA_SMEM);
    cudaFuncSetAttribute(nodeB_kernel, cudaFuncAttributeMaxDynamicSharedMemorySize, NODEB_SMEM);

    const int nscan = (NN + 1023) / 1024;   // 98

    zero_kernel<<<(NN + 255) / 256, 256>>>();                                  // 0
    hist_kernel<<<(EE + 255) / 256, 256>>>(dst);                               // 1
    scan1_kernel<<<nscan, 1024>>>();                                           // 2
    scan3_kernel<<<(NN + 255) / 256, 256>>>();                                 // 3
    scatter_kernel<<<(EE + 255) / 256, 256>>>(src, dst);                       // 4
    agg_kernel<<<(NN * 32 + 255) / 256, 256>>>((const float2*)x);              // 5
    nodeA_kernel<<<NBLKA, 256, NODEA_SMEM>>>(W1, b1);                          // 6
    bnfin_kernel<<<1, 128>>>(bng, bnb);                                        // 7
    nodeB_kernel<<<NBLKA, 256, NODEB_SMEM>>>(W2, b2, lng, lnb, out);           // 8
}

// round 9
// speedup vs baseline: 4.7064x; 1.9175x over previous
#include <cuda_runtime.h>
#include <cuda_bf16.h>
#include <math.h>

#define NN 100000
#define DD 64
#define EE 1000000
#define EPSM 1e-7f
#define NBLKN 782    // ceil(NN/128) node-tile blocks

// ---------------- scratch (static __device__, no allocation) ----------------
__device__ int   g_count[NN];
__device__ int   g_incl[NN];
__device__ int   g_bsum[128];
__device__ int   g_offset[NN + 1];
__device__ int   g_cursor[NN];
__device__ int   g_ssrc[EE];
__device__ float g_aggout[(size_t)NN * DD];      // 25.6 MB (agg + residual)
__device__ float g_h[(size_t)NN * 128];          // 51.2 MB hidden (pre-BN)
__device__ float g_part[(size_t)NBLKN * 256];    // per-block BN partials
__device__ float g_bnscale[128], g_bnshift[128];

// ---------------- tf32 mma helpers ----------------
__device__ __forceinline__ unsigned tf32_of(float f) {
    unsigned u; asm("cvt.rna.tf32.f32 %0, %1;" : "=r"(u) : "f"(f)); return u;
}
__device__ __forceinline__ void mma_tf32(float& d0, float& d1, float& d2, float& d3,
                                         unsigned a0, unsigned a1, unsigned a2, unsigned a3,
                                         unsigned b0, unsigned b1) {
    asm("mma.sync.aligned.m16n8k8.row.col.f32.tf32.tf32.f32 "
        "{%0,%1,%2,%3}, {%4,%5,%6,%7}, {%8,%9}, {%0,%1,%2,%3};"
        : "+f"(d0), "+f"(d1), "+f"(d2), "+f"(d3)
        : "r"(a0), "r"(a1), "r"(a2), "r"(a3), "r"(b0), "r"(b1));
}

// ---------------- 0: zero counters ----------------
__global__ void zero_kernel() {
    unsigned i = blockIdx.x * blockDim.x + threadIdx.x;
    if (i < NN) g_count[i] = 0;
}

// ---------------- 1: histogram of dst ----------------
__global__ void hist_kernel(const int* __restrict__ dst) {
    unsigned e = blockIdx.x * blockDim.x + threadIdx.x;
    if (e < EE) atomicAdd(&g_count[__ldg(dst + e)], 1);
}

// ---------------- 2: per-1024-block inclusive scan ----------------
__global__ void scan1_kernel() {
    __shared__ int s[1024];
    int t = threadIdx.x;
    int i = blockIdx.x * 1024 + t;
    int c = (i < NN) ? g_count[i] : 0;
    s[t] = c;
    __syncthreads();
#pragma unroll
    for (int d = 1; d < 1024; d <<= 1) {
        int v = (t >= d) ? s[t - d] : 0;
        __syncthreads();
        s[t] += v;
        __syncthreads();
    }
    if (i < NN) g_incl[i] = s[t];
    if (t == 1023) g_bsum[blockIdx.x] = s[1023];
}

// ---------------- 3: finalize offsets + cursors (block-prefix fused in) ----------------
__global__ void scan3_kernel() {
    __shared__ int sh[256];
    int t = threadIdx.x;
    int g = blockIdx.x >> 2;           // 1024-group of this 256-block
    sh[t] = (t < g) ? g_bsum[t] : 0;   // g <= 97 < 256
    __syncthreads();
#pragma unroll
    for (int d = 128; d > 0; d >>= 1) {
        if (t < d) sh[t] += sh[t + d];
        __syncthreads();
    }
    int pref = sh[0];
    unsigned i = blockIdx.x * 256 + t;
    if (i < NN) {
        int incl = g_incl[i] + pref;
        g_offset[i + 1] = incl;
        g_cursor[i] = incl - g_count[i];
        if (i == 0) g_offset[0] = 0;
    }
}

// ---------------- 4: scatter edges into CSR order ----------------
__global__ void scatter_kernel(const int* __restrict__ src, const int* __restrict__ dst) {
    unsigned e = blockIdx.x * blockDim.x + threadIdx.x;
    if (e >= EE) return;
    int d = __ldg(dst + e);
    int pos = atomicAdd(&g_cursor[d], 1);
    g_ssrc[pos] = __ldg(src + e);
}

// ---------------- 5: gather-aggregate (warp per node) + residual ----------------
__global__ void __launch_bounds__(256) agg_kernel(const float2* __restrict__ x2) {
    int gw = (blockIdx.x * 256 + threadIdx.x) >> 5;   // node id (uniform per warp)
    int lane = threadIdx.x & 31;
    if (gw >= NN) return;
    int beg = g_offset[gw], end = g_offset[gw + 1];
    float d0 = 0.f, d1 = 0.f, s0 = 0.f, s1 = 0.f;
    for (int base = beg; base < end; base += 32) {
        int m = end - base; if (m > 32) m = 32;
        int sl = (lane < m) ? __ldg(g_ssrc + base + lane) : 0;
#pragma unroll 4
        for (int i = 0; i < m; i++) {
            int s = __shfl_sync(0xFFFFFFFFu, sl, i);
            float2 v = __ldg(x2 + (size_t)s * 32 + lane);
            float m0 = fmaxf(v.x, 0.f) + EPSM;
            float m1 = fmaxf(v.y, 0.f) + EPSM;
            float e0 = __expf(m0), e1 = __expf(m1);
            d0 += e0; d1 += e1;
            s0 = fmaf(m0, e0, s0); s1 = fmaf(m1, e1, s1);
        }
    }
    float2 self = __ldg(x2 + (size_t)gw * 32 + lane);
    float2 r;
    r.x = s0 / (d0 + 1e-16f) + self.x;
    r.y = s1 / (d1 + 1e-16f) + self.y;
    reinterpret_cast<float2*>(g_aggout)[(size_t)gw * 32 + lane] = r;
}

// ---------------- 6: Linear1 via tf32 mma.sync + BN partials ----------------
// 128 nodes/block, 256 threads (8 warps). Warp w -> rows 16w..16w+15, all 128 cols.
// smem: s_a [128][68] tf32, s_w [64][136] tf32, s_red [2][8][128] float.
#define A_PAD 68
#define W1_PAD 136
#define NODEA_SMEM ((128 * A_PAD + 64 * W1_PAD + 2048) * 4)
__global__ void __launch_bounds__(256) nodeA_kernel(const float* __restrict__ W1,
                                                    const float* __restrict__ b1) {
    extern __shared__ __align__(16) unsigned sm_u[];
    unsigned* s_a = sm_u;                          // [128][A_PAD]
    unsigned* s_w = sm_u + 128 * A_PAD;            // [64][W1_PAD]
    float*    s_red = (float*)(sm_u + 128 * A_PAD + 64 * W1_PAD);  // [2][8][128]
    int t = threadIdx.x;
    int nb = blockIdx.x * 128;

    for (int i = t; i < 128 * 64; i += 256) {
        int n = i >> 6, k = i & 63;
        float v = (nb + n < NN) ? g_aggout[(size_t)(nb + n) * 64 + k] : 0.f;
        s_a[n * A_PAD + k] = tf32_of(v);
    }
    for (int i = t; i < 64 * 128; i += 256) {
        int k = i >> 7, c = i & 127;
        s_w[k * W1_PAD + c] = tf32_of(__ldg(W1 + i));
    }
    __syncthreads();

    int lane = t & 31, w = t >> 5;
    int gid = lane >> 2, tig = lane & 3;
    int m0 = w * 16;
    float d[16][4];
#pragma unroll
    for (int nt = 0; nt < 16; nt++) {
        float bA = __ldg(b1 + nt * 8 + 2 * tig);
        float bB = __ldg(b1 + nt * 8 + 2 * tig + 1);
        d[nt][0] = bA; d[nt][1] = bB; d[nt][2] = bA; d[nt][3] = bB;
    }

#pragma unroll
    for (int ks = 0; ks < 8; ks++) {
        int k0 = ks * 8;
        unsigned a0 = s_a[(m0 + gid) * A_PAD + k0 + tig];
        unsigned a1 = s_a[(m0 + gid + 8) * A_PAD + k0 + tig];
        unsigned a2 = s_a[(m0 + gid) * A_PAD + k0 + tig + 4];
        unsigned a3 = s_a[(m0 + gid + 8) * A_PAD + k0 + tig + 4];
#pragma unroll
        for (int nt = 0; nt < 16; nt++) {
            unsigned bb0 = s_w[(k0 + tig) * W1_PAD + nt * 8 + gid];
            unsigned bb1 = s_w[(k0 + tig + 4) * W1_PAD + nt * 8 + gid];
            mma_tf32(d[nt][0], d[nt][1], d[nt][2], d[nt][3], a0, a1, a2, a3, bb0, bb1);
        }
    }

    // epilogue: store h, warp-reduce BN partials per column
    int r0 = nb + m0 + gid, r1 = r0 + 8;
    bool ok0 = r0 < NN, ok1 = r1 < NN;
#pragma unroll
    for (int nt = 0; nt < 16; nt++) {
        float e0 = d[nt][0], e1 = d[nt][1], e2 = d[nt][2], e3 = d[nt][3];
        int cA = nt * 8 + 2 * tig;
        if (ok0) *reinterpret_cast<float2*>(&g_h[(size_t)r0 * 128 + cA]) = make_float2(e0, e1);
        if (ok1) *reinterpret_cast<float2*>(&g_h[(size_t)r1 * 128 + cA]) = make_float2(e2, e3);
        float sA = (ok0 ? e0 : 0.f) + (ok1 ? e2 : 0.f);
        float sB = (ok0 ? e1 : 0.f) + (ok1 ? e3 : 0.f);
        float qA = (ok0 ? e0 * e0 : 0.f) + (ok1 ? e2 * e2 : 0.f);
        float qB = (ok0 ? e1 * e1 : 0.f) + (ok1 ? e3 * e3 : 0.f);
#pragma unroll
        for (int off = 4; off < 32; off <<= 1) {
            sA += __shfl_xor_sync(0xFFFFFFFFu, sA, off);
            sB += __shfl_xor_sync(0xFFFFFFFFu, sB, off);
            qA += __shfl_xor_sync(0xFFFFFFFFu, qA, off);
            qB += __shfl_xor_sync(0xFFFFFFFFu, qB, off);
        }
        if (gid == 0) {
            s_red[w * 128 + cA]          = sA;
            s_red[w * 128 + cA + 1]      = sB;
            s_red[1024 + w * 128 + cA]     = qA;
            s_red[1024 + w * 128 + cA + 1] = qB;
        }
    }
    __syncthreads();
    if (t < 128) {
        float a = 0.f, b = 0.f;
#pragma unroll
        for (int ww = 0; ww < 8; ww++) {
            a += s_red[ww * 128 + t];
            b += s_red[1024 + ww * 128 + t];
        }
        g_part[(size_t)blockIdx.x * 256 + t]       = a;
        g_part[(size_t)blockIdx.x * 256 + 128 + t] = b;
    }
}

// ---------------- 7: BN finalize (parallel reduce of partials) ----------------
__global__ void __launch_bounds__(1024) bnfin_kernel(const float* __restrict__ gam,
                                                     const float* __restrict__ bet) {
    __shared__ float s1[1024], s2[1024];
    int t = threadIdx.x;
    int c = t & 127, seg = t >> 7;   // 8 segments
    float s = 0.f, q = 0.f;
    for (int b = seg; b < NBLKN; b += 8) {
        s += g_part[(size_t)b * 256 + c];
        q += g_part[(size_t)b * 256 + 128 + c];
    }
    s1[t] = s; s2[t] = q;
    __syncthreads();
    if (t < 128) {
        float ss = 0.f, qq = 0.f;
#pragma unroll
        for (int j = 0; j < 8; j++) { ss += s1[j * 128 + t]; qq += s2[j * 128 + t]; }
        float mean = ss * (1.f / (float)NN);
        float var = qq * (1.f / (float)NN) - mean * mean;
        float sc = __ldg(gam + t) * rsqrtf(var + 1e-5f);
        g_bnscale[t] = sc;
        g_bnshift[t] = __ldg(bet + t) - mean * sc;
    }
}

// ---------------- 8: BN+ReLU + Linear2 (tf32 mma) + LayerNorm + ReLU ----------------
// 128 nodes/block, 256 threads. Warp w -> rows 16w..16w+15, all 64 cols.
#define B_APAD 132
#define W2_PAD 72
#define NODEB_SMEM ((128 * B_APAD + 128 * W2_PAD) * 4)
__global__ void __launch_bounds__(256) nodeB_kernel(const float* __restrict__ W2,
                                                    const float* __restrict__ b2,
                                                    const float* __restrict__ lng,
                                                    const float* __restrict__ lnb,
                                                    float* __restrict__ out) {
    extern __shared__ __align__(16) unsigned sm_u[];
    unsigned* s_a = sm_u;                  // [128][B_APAD]
    unsigned* s_w = sm_u + 128 * B_APAD;   // [128][W2_PAD]
    int t = threadIdx.x;
    int nb = blockIdx.x * 128;

    for (int i = t; i < 128 * 128; i += 256) {
        int n = i >> 7, k = i & 127;
        float v = 0.f;
        if (nb + n < NN) {
            v = g_h[(size_t)(nb + n) * 128 + k];
            v = fmaf(v, g_bnscale[k], g_bnshift[k]);
            v = fmaxf(v, 0.f);
        }
        s_a[n * B_APAD + k] = tf32_of(v);
    }
    for (int i = t; i < 128 * 64; i += 256) {
        int k = i >> 6, c = i & 63;
        s_w[k * W2_PAD + c] = tf32_of(__ldg(W2 + i));
    }
    __syncthreads();

    int lane = t & 31, w = t >> 5;
    int gid = lane >> 2, tig = lane & 3;
    int m0 = w * 16;
    float d[8][4];
#pragma unroll
    for (int nt = 0; nt < 8; nt++) {
        float bA = __ldg(b2 + nt * 8 + 2 * tig);
        float bB = __ldg(b2 + nt * 8 + 2 * tig + 1);
        d[nt][0] = bA; d[nt][1] = bB; d[nt][2] = bA; d[nt][3] = bB;
    }

#pragma unroll
    for (int ks = 0; ks < 16; ks++) {
        int k0 = ks * 8;
        unsigned a0 = s_a[(m0 + gid) * B_APAD + k0 + tig];
        unsigned a1 = s_a[(m0 + gid + 8) * B_APAD + k0 + tig];
        unsigned a2 = s_a[(m0 + gid) * B_APAD + k0 + tig + 4];
        unsigned a3 = s_a[(m0 + gid + 8) * B_APAD + k0 + tig + 4];
#pragma unroll
        for (int nt = 0; nt < 8; nt++) {
            unsigned bb0 = s_w[(k0 + tig) * W2_PAD + nt * 8 + gid];
            unsigned bb1 = s_w[(k0 + tig + 4) * W2_PAD + nt * 8 + gid];
            mma_tf32(d[nt][0], d[nt][1], d[nt][2], d[nt][3], a0, a1, a2, a3, bb0, bb1);
        }
    }

    // LayerNorm per row directly on fragments
    float rs0 = 0.f, rq0 = 0.f, rs1 = 0.f, rq1 = 0.f;
#pragma unroll
    for (int nt = 0; nt < 8; nt++) {
        rs0 += d[nt][0] + d[nt][1];
        rq0 += d[nt][0] * d[nt][0] + d[nt][1] * d[nt][1];
        rs1 += d[nt][2] + d[nt][3];
        rq1 += d[nt][2] * d[nt][2] + d[nt][3] * d[nt][3];
    }
#pragma unroll
    for (int off = 1; off < 4; off <<= 1) {
        rs0 += __shfl_xor_sync(0xFFFFFFFFu, rs0, off);
        rq0 += __shfl_xor_sync(0xFFFFFFFFu, rq0, off);
        rs1 += __shfl_xor_sync(0xFFFFFFFFu, rs1, off);
        rq1 += __shfl_xor_sync(0xFFFFFFFFu, rq1, off);
    }
    float mean0 = rs0 * (1.f / 64.f);
    float var0  = rq0 * (1.f / 64.f) - mean0 * mean0;
    float inv0  = rsqrtf(var0 + 1e-5f);
    float mean1 = rs1 * (1.f / 64.f);
    float var1  = rq1 * (1.f / 64.f) - mean1 * mean1;
    float inv1  = rsqrtf(var1 + 1e-5f);

    int r0 = nb + m0 + gid, r1 = r0 + 8;
    bool ok0 = r0 < NN, ok1 = r1 < NN;
#pragma unroll
    for (int nt = 0; nt < 8; nt++) {
        int cA = nt * 8 + 2 * tig;
        float gA = __ldg(lng + cA), gB = __ldg(lng + cA + 1);
        float bA = __ldg(lnb + cA), bB = __ldg(lnb + cA + 1);
        if (ok0) {
            float y0 = fmaxf((d[nt][0] - mean0) * inv0 * gA + bA, 0.f);
            float y1 = fmaxf((d[nt][1] - mean0) * inv0 * gB + bB, 0.f);
            *reinterpret_cast<float2*>(&out[(size_t)r0 * 64 + cA]) = make_float2(y0, y1);
        }
        if (ok1) {
            float y2 = fmaxf((d[nt][2] - mean1) * inv1 * gA + bA, 0.f);
            float y3 = fmaxf((d[nt][3] - mean1) * inv1 * gB + bB, 0.f);
            *reinterpret_cast<float2*>(&out[(size_t)r1 * 64 + cA]) = make_float2(y2, y3);
        }
    }
}

// ---------------- launcher ----------------
extern "C" void kernel_launch(void* const* d_in, const int* in_sizes, int n_in,
                              void* d_out, int out_size) {
    const float* x   = (const float*)d_in[0];
    const int*   ei  = (const int*)d_in[1];
    const float* W1  = (const float*)d_in[2];
    const float* b1  = (const float*)d_in[3];
    const float* bng = (const float*)d_in[4];
    const float* bnb = (const float*)d_in[5];
    const float* W2  = (const float*)d_in[6];
    const float* b2  = (const float*)d_in[7];
    const float* lng = (const float*)d_in[8];
    const float* lnb = (const float*)d_in[9];
    float* out = (float*)d_out;

    const int* src = ei;        // edge_index[0]
    const int* dst = ei + EE;   // edge_index[1]

    cudaFuncSetAttribute(nodeA_kernel, cudaFuncAttributeMaxDynamicSharedMemorySize, NODEA_SMEM);
    cudaFuncSetAttribute(nodeB_kernel, cudaFuncAttributeMaxDynamicSharedMemorySize, NODEB_SMEM);

    const int nscan = (NN + 1023) / 1024;   // 98

    zero_kernel<<<(NN + 255) / 256, 256>>>();                                  // 0
    hist_kernel<<<(EE + 255) / 256, 256>>>(dst);                               // 1
    scan1_kernel<<<nscan, 1024>>>();                                           // 2
    scan3_kernel<<<(NN + 255) / 256, 256>>>();                                 // 3
    scatter_kernel<<<(EE + 255) / 256, 256>>>(src, dst);                       // 4
    agg_kernel<<<(NN * 32 + 255) / 256, 256>>>((const float2*)x);              // 5
    nodeA_kernel<<<NBLKN, 256, NODEA_SMEM>>>(W1, b1);                          // 6
    bnfin_kernel<<<1, 1024>>>(bng, bnb);                                       // 7
    nodeB_kernel<<<NBLKN, 256, NODEB_SMEM>>>(W2, b2, lng, lnb, out);           // 8
}